// round 2
// baseline (speedup 1.0000x reference)
#include <cuda_runtime.h>
#include <math.h>

// ---------------- problem constants ----------------
#define BATCH  4
#define SEQ    1024
#define MEML   1024
#define DMODEL 512
#define NHEAD  8
#define HDIM   64
#define DINNER 1024
#define DSTATE 16
#define DTRANK 32
#define NTOK   (BATCH*SEQ)          // 4096

// ---------------- static scratch (no allocs allowed) ----------------
__device__ float g_q[NTOK*DMODEL];
__device__ float g_k[NTOK*DMODEL];
__device__ float g_v[NTOK*DMODEL];
__device__ float g_scores[(long)BATCH*NHEAD*SEQ*MEML];   // 134 MB
__device__ float g_attn[NTOK*DMODEL];
__device__ float g_tmp[NTOK*DMODEL];
__device__ float g_x1[NTOK*DMODEL];
__device__ float g_xz[NTOK*2*DINNER];
__device__ float g_u[NTOK*DINNER];
__device__ float g_xdbl[NTOK*64];
__device__ float g_dt[NTOK*DINNER];
__device__ float g_yg[NTOK*DINNER];
__device__ float g_m[NTOK*DMODEL];
__device__ float g_x2[NTOK*DMODEL];
__device__ float g_h1[NTOK*2048];

// ---------------- generic NT GEMM:  C[M,N] = alpha * A(MxK) * B(NxK)^T (+bias, act) ------
// act: 0 none, 1 exact gelu, 2 softplus
template<int BM, int BN, int BK, int TM, int TN, int THREADS>
__global__ __launch_bounds__(THREADS) void gemm_nt(
    const float* __restrict__ A, const float* __restrict__ B,
    float* __restrict__ C, const float* __restrict__ bias,
    int M, int N, int K, int lda, int ldb, int ldc,
    float alpha, int act, int zdiv,
    long sAb, long sAh, long sBb, long sBh, long sCb, long sCh)
{
    int z = blockIdx.z;
    int zb = z / zdiv, zh = z - zb*zdiv;
    A += zb*sAb + zh*sAh;
    B += zb*sBb + zh*sBh;
    C += zb*sCb + zh*sCh;

    const int tid = threadIdx.x;
    const int bm = blockIdx.y * BM;
    const int bn = blockIdx.x * BN;

    __shared__ float As[BK][BM+4];
    __shared__ float Bs[BK][BN+4];

    float acc[TM][TN];
#pragma unroll
    for (int i = 0; i < TM; i++)
#pragma unroll
        for (int j = 0; j < TN; j++) acc[i][j] = 0.f;

    const int NTG = BN / TN;
    const int tm = (tid / NTG) * TM;
    const int tn = (tid % NTG) * TN;

    for (int k0 = 0; k0 < K; k0 += BK) {
        // load A tile (always in-bounds: M,K multiples of BM,BK in this problem)
#pragma unroll
        for (int t = 0; t < (BM*BK/4)/THREADS; t++) {
            int idx = tid + t*THREADS;
            int r = idx / (BK/4), c4 = (idx % (BK/4))*4;
            float4 v = *(const float4*)&A[(long)(bm + r)*lda + k0 + c4];
            As[c4+0][r] = v.x; As[c4+1][r] = v.y; As[c4+2][r] = v.z; As[c4+3][r] = v.w;
        }
        // load B tile (guard n < N)
#pragma unroll
        for (int t = 0; t < (BN*BK/4)/THREADS; t++) {
            int idx = tid + t*THREADS;
            int r = idx / (BK/4), c4 = (idx % (BK/4))*4;
            int n = bn + r;
            float4 v = make_float4(0.f,0.f,0.f,0.f);
            if (n < N) v = *(const float4*)&B[(long)n*ldb + k0 + c4];
            Bs[c4+0][r] = v.x; Bs[c4+1][r] = v.y; Bs[c4+2][r] = v.z; Bs[c4+3][r] = v.w;
        }
        __syncthreads();
#pragma unroll
        for (int kk = 0; kk < BK; kk++) {
            float a[TM], b[TN];
#pragma unroll
            for (int i = 0; i < TM; i++) a[i] = As[kk][tm+i];
#pragma unroll
            for (int j = 0; j < TN; j++) b[j] = Bs[kk][tn+j];
#pragma unroll
            for (int i = 0; i < TM; i++)
#pragma unroll
                for (int j = 0; j < TN; j++) acc[i][j] = fmaf(a[i], b[j], acc[i][j]);
        }
        __syncthreads();
    }

#pragma unroll
    for (int i = 0; i < TM; i++) {
#pragma unroll
        for (int j = 0; j < TN; j++) {
            int n = bn + tn + j;
            if (n < N) {
                float v = acc[i][j] * alpha;
                if (bias) v += bias[n];
                if (act == 1) v = 0.5f * v * (1.f + erff(v * 0.70710678118654752f));
                else if (act == 2) v = (v > 20.f) ? v : log1pf(expf(v));
                C[(long)(bm + tm + i)*ldc + n] = v;
            }
        }
    }
}

// ---------------- softmax over rows of length 1024 (in-place) ----------------
__global__ __launch_bounds__(256) void softmax_rows(float* __restrict__ S)
{
    long row = blockIdx.x;
    float4* p = (float4*)(S + row*1024);
    int tid = threadIdx.x;
    float4 v = p[tid];
    float m = fmaxf(fmaxf(v.x, v.y), fmaxf(v.z, v.w));
#pragma unroll
    for (int o = 16; o; o >>= 1) m = fmaxf(m, __shfl_xor_sync(0xffffffffu, m, o));
    __shared__ float sm[8], ss[8];
    int w = tid >> 5;
    if ((tid & 31) == 0) sm[w] = m;
    __syncthreads();
    float mm = sm[0];
#pragma unroll
    for (int i = 1; i < 8; i++) mm = fmaxf(mm, sm[i]);
    v.x = __expf(v.x - mm); v.y = __expf(v.y - mm);
    v.z = __expf(v.z - mm); v.w = __expf(v.w - mm);
    float s = v.x + v.y + v.z + v.w;
#pragma unroll
    for (int o = 16; o; o >>= 1) s += __shfl_xor_sync(0xffffffffu, s, o);
    if ((tid & 31) == 0) ss[w] = s;
    __syncthreads();
    float tot = 0.f;
#pragma unroll
    for (int i = 0; i < 8; i++) tot += ss[i];
    float inv = 1.f / tot;
    v.x *= inv; v.y *= inv; v.z *= inv; v.w *= inv;
    p[tid] = v;
}

// ---------------- PV:  O[b,q,h*64+d] = sum_k P[bh,q,k] * V[b,k,h*64+d] ----------------
__global__ __launch_bounds__(256) void attn_pv(const float* __restrict__ P,
                                               const float* __restrict__ V,
                                               float* __restrict__ O)
{
    int z = blockIdx.z, b = z >> 3, h = z & 7;
    const float* Pp = P + (long)z * SEQ * MEML;
    const float* Vp = V + (long)b*MEML*DMODEL + h*HDIM;
    float*       Op = O + (long)b*SEQ*DMODEL + h*HDIM;
    int q0 = blockIdx.x * 128;
    int tid = threadIdx.x;
    __shared__ float As[16][132];
    __shared__ float Bs[16][68];
    int tm = (tid / 16) * 8, tn = (tid % 16) * 4;
    float acc[8][4];
#pragma unroll
    for (int i = 0; i < 8; i++)
#pragma unroll
        for (int j = 0; j < 4; j++) acc[i][j] = 0.f;

    for (int k0 = 0; k0 < MEML; k0 += 16) {
#pragma unroll
        for (int t = 0; t < 2; t++) {
            int idx = tid + t*256;
            int r = idx >> 2, c4 = (idx & 3) << 2;
            float4 v = *(const float4*)&Pp[(long)(q0 + r)*MEML + k0 + c4];
            As[c4+0][r] = v.x; As[c4+1][r] = v.y; As[c4+2][r] = v.z; As[c4+3][r] = v.w;
        }
        {
            int r = tid >> 4, c4 = (tid & 15) << 2;
            float4 v = *(const float4*)&Vp[(long)(k0 + r)*DMODEL + c4];
            *(float4*)&Bs[r][c4] = v;
        }
        __syncthreads();
#pragma unroll
        for (int kk = 0; kk < 16; kk++) {
            float a[8], bb[4];
#pragma unroll
            for (int i = 0; i < 8; i++) a[i] = As[kk][tm+i];
#pragma unroll
            for (int j = 0; j < 4; j++) bb[j] = Bs[kk][tn+j];
#pragma unroll
            for (int i = 0; i < 8; i++)
#pragma unroll
                for (int j = 0; j < 4; j++) acc[i][j] = fmaf(a[i], bb[j], acc[i][j]);
        }
        __syncthreads();
    }
#pragma unroll
    for (int i = 0; i < 8; i++)
#pragma unroll
        for (int j = 0; j < 4; j++)
            Op[(long)(q0 + tm + i)*DMODEL + tn + j] = acc[i][j];
}

// ---------------- LayerNorm(a + r) ----------------
__global__ __launch_bounds__(128) void ln_residual(const float* __restrict__ a,
                                                   const float* __restrict__ r,
                                                   const float* __restrict__ g,
                                                   const float* __restrict__ be,
                                                   float* __restrict__ o)
{
    long row = blockIdx.x;
    int tid = threadIdx.x;
    float4 va = ((const float4*)(a + row*DMODEL))[tid];
    float4 vr = ((const float4*)(r + row*DMODEL))[tid];
    float x0 = va.x+vr.x, x1 = va.y+vr.y, x2 = va.z+vr.z, x3 = va.w+vr.w;
    float s = x0+x1+x2+x3;
    float q = x0*x0 + x1*x1 + x2*x2 + x3*x3;
#pragma unroll
    for (int of = 16; of; of >>= 1) {
        s += __shfl_xor_sync(0xffffffffu, s, of);
        q += __shfl_xor_sync(0xffffffffu, q, of);
    }
    __shared__ float s1[4], s2[4];
    int w = tid >> 5;
    if ((tid & 31) == 0) { s1[w] = s; s2[w] = q; }
    __syncthreads();
    float ts = s1[0]+s1[1]+s1[2]+s1[3];
    float tq = s2[0]+s2[1]+s2[2]+s2[3];
    float mean = ts * (1.f/DMODEL);
    float var  = tq * (1.f/DMODEL) - mean*mean;
    float rstd = rsqrtf(var + 1e-5f);
    float4 vg = ((const float4*)g)[tid];
    float4 vb = ((const float4*)be)[tid];
    float4 out;
    out.x = (x0-mean)*rstd*vg.x + vb.x;
    out.y = (x1-mean)*rstd*vg.y + vb.y;
    out.z = (x2-mean)*rstd*vg.z + vb.z;
    out.w = (x3-mean)*rstd*vg.w + vb.w;
    ((float4*)(o + row*DMODEL))[tid] = out;
}

// ---------------- depthwise causal conv (D_CONV=4) + SiLU ----------------
__global__ void conv_silu(const float* __restrict__ xz, const float* __restrict__ w,
                          const float* __restrict__ cb, float* __restrict__ u)
{
    long idx = (long)blockIdx.x * 256 + threadIdx.x;   // over NTOK*DINNER
    int d = (int)(idx & (DINNER-1));
    long n = idx >> 10;                // b*SEQ + l
    int l = (int)(n & (SEQ-1));
    float acc = cb[d];
#pragma unroll
    for (int j = 0; j < 4; j++) {
        int ll = l - 3 + j;
        if (ll >= 0) acc += w[d*4 + j] * xz[(n - 3 + j)*2048 + d];
    }
    u[idx] = acc / (1.f + __expf(-acc));   // silu
}

// ---------------- selective scan + D skip + SiLU(z) gating ----------------
// thread <-> channel (b, d); 16 states in registers; B/C rows double-buffered in smem
__global__ __launch_bounds__(128) void scan_kernel(
    const float* __restrict__ xdbl, const float* __restrict__ dt,
    const float* __restrict__ u, const float* __restrict__ xz,
    const float* __restrict__ A_log, const float* __restrict__ D_p,
    float* __restrict__ yg)
{
    int b = blockIdx.x;
    int d = blockIdx.y * 128 + threadIdx.x;
    float A[DSTATE], h[DSTATE];
#pragma unroll
    for (int s = 0; s < DSTATE; s++) { A[s] = -expf(A_log[d*DSTATE + s]); h[s] = 0.f; }
    float Dd = D_p[d];
    __shared__ float sBC[2][32];
    if (threadIdx.x < 32)
        sBC[0][threadIdx.x] = xdbl[((long)b*SEQ + 0)*64 + 32 + threadIdx.x];
    __syncthreads();
    for (int l = 0; l < SEQ; l++) {
        int buf = l & 1;
        if (l + 1 < SEQ && threadIdx.x < 32)
            sBC[buf^1][threadIdx.x] = xdbl[((long)b*SEQ + l + 1)*64 + 32 + threadIdx.x];
        long nrow = (long)b*SEQ + l;
        float dtv = dt[nrow*DINNER + d];
        float uv  = u[nrow*DINNER + d];
        float zv  = xz[nrow*2048 + DINNER + d];
        float y = 0.f;
#pragma unroll
        for (int s = 0; s < DSTATE; s++) {
            float dA = __expf(dtv * A[s]);
            h[s] = h[s]*dA + dtv * sBC[buf][s] * uv;
            y = fmaf(h[s], sBC[buf][16+s], y);
        }
        y += uv * Dd;
        float sg = zv / (1.f + __expf(-zv));
        yg[nrow*DINNER + d] = y * sg;
        __syncthreads();
    }
}

// ---------------- host launcher ----------------
extern "C" void kernel_launch(void* const* d_in, const int* in_sizes, int n_in,
                              void* d_out, int out_size)
{
    const float* x       = (const float*)d_in[0];
    const float* memory  = (const float*)d_in[1];
    const float* Wq      = (const float*)d_in[2];
    const float* bq      = (const float*)d_in[3];
    const float* Wk      = (const float*)d_in[4];
    const float* bk      = (const float*)d_in[5];
    const float* Wv      = (const float*)d_in[6];
    const float* bv      = (const float*)d_in[7];
    const float* Wo      = (const float*)d_in[8];
    const float* bo      = (const float*)d_in[9];
    const float* ln1_g   = (const float*)d_in[10];
    const float* ln1_b   = (const float*)d_in[11];
    const float* ln2_g   = (const float*)d_in[12];
    const float* ln2_b   = (const float*)d_in[13];
    const float* ln3_g   = (const float*)d_in[14];
    const float* ln3_b   = (const float*)d_in[15];
    const float* W_in    = (const float*)d_in[16];
    const float* conv_w  = (const float*)d_in[17];
    const float* conv_b  = (const float*)d_in[18];
    const float* W_xproj = (const float*)d_in[19];
    const float* W_dt    = (const float*)d_in[20];
    const float* b_dt    = (const float*)d_in[21];
    const float* A_log   = (const float*)d_in[22];
    const float* D_p     = (const float*)d_in[23];
    const float* W_out   = (const float*)d_in[24];
    const float* W1      = (const float*)d_in[25];
    const float* b1      = (const float*)d_in[26];
    const float* W2      = (const float*)d_in[27];
    const float* b2      = (const float*)d_in[28];
    float* out = (float*)d_out;

    void* p;
    cudaGetSymbolAddress(&p, g_q);      float* q_    = (float*)p;
    cudaGetSymbolAddress(&p, g_k);      float* k_    = (float*)p;
    cudaGetSymbolAddress(&p, g_v);      float* v_    = (float*)p;
    cudaGetSymbolAddress(&p, g_scores); float* sc_   = (float*)p;
    cudaGetSymbolAddress(&p, g_attn);   float* attn_ = (float*)p;
    cudaGetSymbolAddress(&p, g_tmp);    float* tmp_  = (float*)p;
    cudaGetSymbolAddress(&p, g_x1);     float* x1_   = (float*)p;
    cudaGetSymbolAddress(&p, g_xz);     float* xz_   = (float*)p;
    cudaGetSymbolAddress(&p, g_u);      float* u_    = (float*)p;
    cudaGetSymbolAddress(&p, g_xdbl);   float* xd_   = (float*)p;
    cudaGetSymbolAddress(&p, g_dt);     float* dt_   = (float*)p;
    cudaGetSymbolAddress(&p, g_yg);     float* yg_   = (float*)p;
    cudaGetSymbolAddress(&p, g_m);      float* m_    = (float*)p;
    cudaGetSymbolAddress(&p, g_x2);     float* x2_   = (float*)p;
    cudaGetSymbolAddress(&p, g_h1);     float* h1_   = (float*)p;

    // ---- cross attention ----
    // q/k/v projections (NT GEMM, M=4096, N=512, K=512)
    gemm_nt<128,128,16,8,8,256><<<dim3(4,32,1),256>>>(x,      Wq, q_, bq, NTOK,512,512, 512,512,512, 1.f,0,1, 0,0,0,0,0,0);
    gemm_nt<128,128,16,8,8,256><<<dim3(4,32,1),256>>>(memory, Wk, k_, bk, NTOK,512,512, 512,512,512, 1.f,0,1, 0,0,0,0,0,0);
    gemm_nt<128,128,16,8,8,256><<<dim3(4,32,1),256>>>(memory, Wv, v_, bv, NTOK,512,512, 512,512,512, 1.f,0,1, 0,0,0,0,0,0);
    // scores: per (b,h) 1024x1024x64, scaled by 1/8
    gemm_nt<128,128,16,8,8,256><<<dim3(8,8,32),256>>>(q_, k_, sc_, nullptr,
        1024,1024,64, 512,512,1024, 0.125f,0, NHEAD,
        (long)SEQ*DMODEL, (long)HDIM, (long)MEML*DMODEL, (long)HDIM,
        (long)NHEAD*SEQ*MEML, (long)SEQ*MEML);
    softmax_rows<<<BATCH*NHEAD*SEQ,256>>>(sc_);
    attn_pv<<<dim3(8,1,32),256>>>(sc_, v_, attn_);
    // output projection + residual LN
    gemm_nt<128,128,16,8,8,256><<<dim3(4,32,1),256>>>(attn_, Wo, tmp_, bo, NTOK,512,512, 512,512,512, 1.f,0,1, 0,0,0,0,0,0);
    ln_residual<<<NTOK,128>>>(x, tmp_, ln1_g, ln1_b, x1_);

    // ---- mamba ----
    gemm_nt<128,128,16,8,8,256><<<dim3(16,32,1),256>>>(x1_, W_in, xz_, nullptr, NTOK,2048,512, 512,512,2048, 1.f,0,1, 0,0,0,0,0,0);
    conv_silu<<<(NTOK*DINNER)/256,256>>>(xz_, conv_w, conv_b, u_);
    gemm_nt<64,64,16,4,4,256><<<dim3(1,64,1),256>>>(u_, W_xproj, xd_, nullptr, NTOK,64,1024, 1024,1024,64, 1.f,0,1, 0,0,0,0,0,0);
    gemm_nt<128,128,16,8,8,256><<<dim3(8,32,1),256>>>(xd_, W_dt, dt_, b_dt, NTOK,1024,32, 64,32,1024, 1.f,2,1, 0,0,0,0,0,0);
    scan_kernel<<<dim3(BATCH,DINNER/128),128>>>(xd_, dt_, u_, xz_, A_log, D_p, yg_);
    gemm_nt<128,128,16,8,8,256><<<dim3(4,32,1),256>>>(yg_, W_out, m_, nullptr, NTOK,512,1024, 1024,1024,512, 1.f,0,1, 0,0,0,0,0,0);
    ln_residual<<<NTOK,128>>>(x1_, m_, ln2_g, ln2_b, x2_);

    // ---- FFN ----
    gemm_nt<128,128,16,8,8,256><<<dim3(16,32,1),256>>>(x2_, W1, h1_, b1, NTOK,2048,512, 512,512,2048, 1.f,1,1, 0,0,0,0,0,0);
    gemm_nt<128,128,16,8,8,256><<<dim3(4,32,1),256>>>(h1_, W2, tmp_, b2, NTOK,512,2048, 2048,2048,512, 1.f,0,1, 0,0,0,0,0,0);
    ln_residual<<<NTOK,128>>>(x2_, tmp_, ln3_g, ln3_b, out);
}

// round 3
// speedup vs baseline: 1.0023x; 1.0023x over previous
#include <cuda_runtime.h>
#include <math.h>

// ---------------- problem constants ----------------
#define BATCH  4
#define SEQ    1024
#define MEML   1024
#define DMODEL 512
#define NHEAD  8
#define HDIM   64
#define DINNER 1024
#define DSTATE 16
#define DTRANK 32
#define NTOK   (BATCH*SEQ)          // 4096

// ---------------- static scratch (no allocs allowed) ----------------
__device__ float g_q[NTOK*DMODEL];
__device__ float g_k[NTOK*DMODEL];
__device__ float g_v[NTOK*DMODEL];
__device__ float g_scores[(long)BATCH*NHEAD*SEQ*MEML];   // 134 MB
__device__ float g_attn[NTOK*DMODEL];
__device__ float g_tmp[NTOK*DMODEL];
__device__ float g_x1[NTOK*DMODEL];
__device__ float g_xz[NTOK*2*DINNER];
__device__ float g_u[NTOK*DINNER];
__device__ float g_xdbl[NTOK*64];
__device__ float g_dt[NTOK*DINNER];
__device__ float g_yg[NTOK*DINNER];
__device__ float g_m[NTOK*DMODEL];
__device__ float g_x2[NTOK*DMODEL];
__device__ float g_h1[NTOK*2048];

// ---------------- generic NT GEMM:  C[M,N] = alpha * A(MxK) * B(NxK)^T (+bias, act) ------
// act: 0 none, 1 exact gelu, 2 softplus
template<int BM, int BN, int BK, int TM, int TN, int THREADS>
__global__ __launch_bounds__(THREADS) void gemm_nt(
    const float* __restrict__ A, const float* __restrict__ B,
    float* __restrict__ C, const float* __restrict__ bias,
    int M, int N, int K, int lda, int ldb, int ldc,
    float alpha, int act, int zdiv,
    long sAb, long sAh, long sBb, long sBh, long sCb, long sCh)
{
    int z = blockIdx.z;
    int zb = z / zdiv, zh = z - zb*zdiv;
    A += zb*sAb + zh*sAh;
    B += zb*sBb + zh*sBh;
    C += zb*sCb + zh*sCh;

    const int tid = threadIdx.x;
    const int bm = blockIdx.y * BM;
    const int bn = blockIdx.x * BN;

    __shared__ float As[BK][BM+4];
    __shared__ float Bs[BK][BN+4];

    float acc[TM][TN];
#pragma unroll
    for (int i = 0; i < TM; i++)
#pragma unroll
        for (int j = 0; j < TN; j++) acc[i][j] = 0.f;

    const int NTG = BN / TN;
    const int tm = (tid / NTG) * TM;
    const int tn = (tid % NTG) * TN;

    for (int k0 = 0; k0 < K; k0 += BK) {
        // load A tile (always in-bounds: M,K multiples of BM,BK in this problem)
#pragma unroll
        for (int t = 0; t < (BM*BK/4)/THREADS; t++) {
            int idx = tid + t*THREADS;
            int r = idx / (BK/4), c4 = (idx % (BK/4))*4;
            float4 v = *(const float4*)&A[(long)(bm + r)*lda + k0 + c4];
            As[c4+0][r] = v.x; As[c4+1][r] = v.y; As[c4+2][r] = v.z; As[c4+3][r] = v.w;
        }
        // load B tile (guard n < N)
#pragma unroll
        for (int t = 0; t < (BN*BK/4)/THREADS; t++) {
            int idx = tid + t*THREADS;
            int r = idx / (BK/4), c4 = (idx % (BK/4))*4;
            int n = bn + r;
            float4 v = make_float4(0.f,0.f,0.f,0.f);
            if (n < N) v = *(const float4*)&B[(long)n*ldb + k0 + c4];
            Bs[c4+0][r] = v.x; Bs[c4+1][r] = v.y; Bs[c4+2][r] = v.z; Bs[c4+3][r] = v.w;
        }
        __syncthreads();
#pragma unroll
        for (int kk = 0; kk < BK; kk++) {
            float a[TM], b[TN];
#pragma unroll
            for (int i = 0; i < TM; i++) a[i] = As[kk][tm+i];
#pragma unroll
            for (int j = 0; j < TN; j++) b[j] = Bs[kk][tn+j];
#pragma unroll
            for (int i = 0; i < TM; i++)
#pragma unroll
                for (int j = 0; j < TN; j++) acc[i][j] = fmaf(a[i], b[j], acc[i][j]);
        }
        __syncthreads();
    }

#pragma unroll
    for (int i = 0; i < TM; i++) {
#pragma unroll
        for (int j = 0; j < TN; j++) {
            int n = bn + tn + j;
            if (n < N) {
                float v = acc[i][j] * alpha;
                if (bias) v += bias[n];
                if (act == 1) v = 0.5f * v * (1.f + erff(v * 0.70710678118654752f));
                else if (act == 2) v = (v > 20.f) ? v : log1pf(expf(v));
                C[(long)(bm + tm + i)*ldc + n] = v;
            }
        }
    }
}

// ---------------- softmax over rows of length 1024 (in-place) ----------------
__global__ __launch_bounds__(256) void softmax_rows(float* __restrict__ S)
{
    long row = blockIdx.x;
    float4* p = (float4*)(S + row*1024);
    int tid = threadIdx.x;
    float4 v = p[tid];
    float m = fmaxf(fmaxf(v.x, v.y), fmaxf(v.z, v.w));
#pragma unroll
    for (int o = 16; o; o >>= 1) m = fmaxf(m, __shfl_xor_sync(0xffffffffu, m, o));
    __shared__ float sm[8], ss[8];
    int w = tid >> 5;
    if ((tid & 31) == 0) sm[w] = m;
    __syncthreads();
    float mm = sm[0];
#pragma unroll
    for (int i = 1; i < 8; i++) mm = fmaxf(mm, sm[i]);
    v.x = __expf(v.x - mm); v.y = __expf(v.y - mm);
    v.z = __expf(v.z - mm); v.w = __expf(v.w - mm);
    float s = v.x + v.y + v.z + v.w;
#pragma unroll
    for (int o = 16; o; o >>= 1) s += __shfl_xor_sync(0xffffffffu, s, o);
    if ((tid & 31) == 0) ss[w] = s;
    __syncthreads();
    float tot = 0.f;
#pragma unroll
    for (int i = 0; i < 8; i++) tot += ss[i];
    float inv = 1.f / tot;
    v.x *= inv; v.y *= inv; v.z *= inv; v.w *= inv;
    p[tid] = v;
}

// ---------------- PV:  O[b,q,h*64+d] = sum_k P[bh,q,k] * V[b,k,h*64+d] ----------------
__global__ __launch_bounds__(256) void attn_pv(const float* __restrict__ P,
                                               const float* __restrict__ V,
                                               float* __restrict__ O)
{
    int z = blockIdx.z, b = z >> 3, h = z & 7;
    const float* Pp = P + (long)z * SEQ * MEML;
    const float* Vp = V + (long)b*MEML*DMODEL + h*HDIM;
    float*       Op = O + (long)b*SEQ*DMODEL + h*HDIM;
    int q0 = blockIdx.x * 128;
    int tid = threadIdx.x;
    __shared__ float As[16][132];
    __shared__ float Bs[16][68];
    int tm = (tid / 16) * 8, tn = (tid % 16) * 4;
    float acc[8][4];
#pragma unroll
    for (int i = 0; i < 8; i++)
#pragma unroll
        for (int j = 0; j < 4; j++) acc[i][j] = 0.f;

    for (int k0 = 0; k0 < MEML; k0 += 16) {
#pragma unroll
        for (int t = 0; t < 2; t++) {
            int idx = tid + t*256;
            int r = idx >> 2, c4 = (idx & 3) << 2;
            float4 v = *(const float4*)&Pp[(long)(q0 + r)*MEML + k0 + c4];
            As[c4+0][r] = v.x; As[c4+1][r] = v.y; As[c4+2][r] = v.z; As[c4+3][r] = v.w;
        }
        {
            int r = tid >> 4, c4 = (tid & 15) << 2;
            float4 v = *(const float4*)&Vp[(long)(k0 + r)*DMODEL + c4];
            *(float4*)&Bs[r][c4] = v;
        }
        __syncthreads();
#pragma unroll
        for (int kk = 0; kk < 16; kk++) {
            float a[8], bb[4];
#pragma unroll
            for (int i = 0; i < 8; i++) a[i] = As[kk][tm+i];
#pragma unroll
            for (int j = 0; j < 4; j++) bb[j] = Bs[kk][tn+j];
#pragma unroll
            for (int i = 0; i < 8; i++)
#pragma unroll
                for (int j = 0; j < 4; j++) acc[i][j] = fmaf(a[i], bb[j], acc[i][j]);
        }
        __syncthreads();
    }
#pragma unroll
    for (int i = 0; i < 8; i++)
#pragma unroll
        for (int j = 0; j < 4; j++)
            Op[(long)(q0 + tm + i)*DMODEL + tn + j] = acc[i][j];
}

// ---------------- LayerNorm(a + r) ----------------
__global__ __launch_bounds__(128) void ln_residual(const float* __restrict__ a,
                                                   const float* __restrict__ r,
                                                   const float* __restrict__ g,
                                                   const float* __restrict__ be,
                                                   float* __restrict__ o)
{
    long row = blockIdx.x;
    int tid = threadIdx.x;
    float4 va = ((const float4*)(a + row*DMODEL))[tid];
    float4 vr = ((const float4*)(r + row*DMODEL))[tid];
    float x0 = va.x+vr.x, x1 = va.y+vr.y, x2 = va.z+vr.z, x3 = va.w+vr.w;
    float s = x0+x1+x2+x3;
    float q = x0*x0 + x1*x1 + x2*x2 + x3*x3;
#pragma unroll
    for (int of = 16; of; of >>= 1) {
        s += __shfl_xor_sync(0xffffffffu, s, of);
        q += __shfl_xor_sync(0xffffffffu, q, of);
    }
    __shared__ float s1[4], s2[4];
    int w = tid >> 5;
    if ((tid & 31) == 0) { s1[w] = s; s2[w] = q; }
    __syncthreads();
    float ts = s1[0]+s1[1]+s1[2]+s1[3];
    float tq = s2[0]+s2[1]+s2[2]+s2[3];
    float mean = ts * (1.f/DMODEL);
    float var  = tq * (1.f/DMODEL) - mean*mean;
    float rstd = rsqrtf(var + 1e-5f);
    float4 vg = ((const float4*)g)[tid];
    float4 vb = ((const float4*)be)[tid];
    float4 out;
    out.x = (x0-mean)*rstd*vg.x + vb.x;
    out.y = (x1-mean)*rstd*vg.y + vb.y;
    out.z = (x2-mean)*rstd*vg.z + vb.z;
    out.w = (x3-mean)*rstd*vg.w + vb.w;
    ((float4*)(o + row*DMODEL))[tid] = out;
}

// ---------------- depthwise causal conv (D_CONV=4) + SiLU ----------------
__global__ void conv_silu(const float* __restrict__ xz, const float* __restrict__ w,
                          const float* __restrict__ cb, float* __restrict__ u)
{
    long idx = (long)blockIdx.x * 256 + threadIdx.x;   // over NTOK*DINNER
    int d = (int)(idx & (DINNER-1));
    long n = idx >> 10;                // b*SEQ + l
    int l = (int)(n & (SEQ-1));
    float acc = cb[d];
#pragma unroll
    for (int j = 0; j < 4; j++) {
        int ll = l - 3 + j;
        if (ll >= 0) acc += w[d*4 + j] * xz[(n - 3 + j)*2048 + d];
    }
    u[idx] = acc / (1.f + __expf(-acc));   // silu
}

// ---------------- selective scan + D skip + SiLU(z) gating ----------------
// thread <-> channel (b, d); 16 states in registers; B/C rows double-buffered in smem
__global__ __launch_bounds__(128) void scan_kernel(
    const float* __restrict__ xdbl, const float* __restrict__ dt,
    const float* __restrict__ u, const float* __restrict__ xz,
    const float* __restrict__ A_log, const float* __restrict__ D_p,
    float* __restrict__ yg)
{
    int b = blockIdx.x;
    int d = blockIdx.y * 128 + threadIdx.x;
    float A[DSTATE], h[DSTATE];
#pragma unroll
    for (int s = 0; s < DSTATE; s++) { A[s] = -expf(A_log[d*DSTATE + s]); h[s] = 0.f; }
    float Dd = D_p[d];
    __shared__ float sBC[2][32];
    if (threadIdx.x < 32)
        sBC[0][threadIdx.x] = xdbl[((long)b*SEQ + 0)*64 + 32 + threadIdx.x];
    __syncthreads();
    for (int l = 0; l < SEQ; l++) {
        int buf = l & 1;
        if (l + 1 < SEQ && threadIdx.x < 32)
            sBC[buf^1][threadIdx.x] = xdbl[((long)b*SEQ + l + 1)*64 + 32 + threadIdx.x];
        long nrow = (long)b*SEQ + l;
        float dtv = dt[nrow*DINNER + d];
        float uv  = u[nrow*DINNER + d];
        float zv  = xz[nrow*2048 + DINNER + d];
        float y = 0.f;
#pragma unroll
        for (int s = 0; s < DSTATE; s++) {
            float dA = __expf(dtv * A[s]);
            h[s] = h[s]*dA + dtv * sBC[buf][s] * uv;
            y = fmaf(h[s], sBC[buf][16+s], y);
        }
        y += uv * Dd;
        float sg = zv / (1.f + __expf(-zv));
        yg[nrow*DINNER + d] = y * sg;
        __syncthreads();
    }
}

// ---------------- host launcher ----------------
extern "C" void kernel_launch(void* const* d_in, const int* in_sizes, int n_in,
                              void* d_out, int out_size)
{
    const float* x       = (const float*)d_in[0];
    const float* memory  = (const float*)d_in[1];
    const float* Wq      = (const float*)d_in[2];
    const float* bq      = (const float*)d_in[3];
    const float* Wk      = (const float*)d_in[4];
    const float* bk      = (const float*)d_in[5];
    const float* Wv      = (const float*)d_in[6];
    const float* bv      = (const float*)d_in[7];
    const float* Wo      = (const float*)d_in[8];
    const float* bo      = (const float*)d_in[9];
    const float* ln1_g   = (const float*)d_in[10];
    const float* ln1_b   = (const float*)d_in[11];
    const float* ln2_g   = (const float*)d_in[12];
    const float* ln2_b   = (const float*)d_in[13];
    const float* ln3_g   = (const float*)d_in[14];
    const float* ln3_b   = (const float*)d_in[15];
    const float* W_in    = (const float*)d_in[16];
    const float* conv_w  = (const float*)d_in[17];
    const float* conv_b  = (const float*)d_in[18];
    const float* W_xproj = (const float*)d_in[19];
    const float* W_dt    = (const float*)d_in[20];
    const float* b_dt    = (const float*)d_in[21];
    const float* A_log   = (const float*)d_in[22];
    const float* D_p     = (const float*)d_in[23];
    const float* W_out   = (const float*)d_in[24];
    const float* W1      = (const float*)d_in[25];
    const float* b1      = (const float*)d_in[26];
    const float* W2      = (const float*)d_in[27];
    const float* b2      = (const float*)d_in[28];
    float* out = (float*)d_out;

    void* p;
    cudaGetSymbolAddress(&p, g_q);      float* q_    = (float*)p;
    cudaGetSymbolAddress(&p, g_k);      float* k_    = (float*)p;
    cudaGetSymbolAddress(&p, g_v);      float* v_    = (float*)p;
    cudaGetSymbolAddress(&p, g_scores); float* sc_   = (float*)p;
    cudaGetSymbolAddress(&p, g_attn);   float* attn_ = (float*)p;
    cudaGetSymbolAddress(&p, g_tmp);    float* tmp_  = (float*)p;
    cudaGetSymbolAddress(&p, g_x1);     float* x1_   = (float*)p;
    cudaGetSymbolAddress(&p, g_xz);     float* xz_   = (float*)p;
    cudaGetSymbolAddress(&p, g_u);      float* u_    = (float*)p;
    cudaGetSymbolAddress(&p, g_xdbl);   float* xd_   = (float*)p;
    cudaGetSymbolAddress(&p, g_dt);     float* dt_   = (float*)p;
    cudaGetSymbolAddress(&p, g_yg);     float* yg_   = (float*)p;
    cudaGetSymbolAddress(&p, g_m);      float* m_    = (float*)p;
    cudaGetSymbolAddress(&p, g_x2);     float* x2_   = (float*)p;
    cudaGetSymbolAddress(&p, g_h1);     float* h1_   = (float*)p;

    // ---- cross attention ----
    // q/k/v projections (NT GEMM, M=4096, N=512, K=512)
    gemm_nt<128,128,16,8,8,256><<<dim3(4,32,1),256>>>(x,      Wq, q_, bq, NTOK,512,512, 512,512,512, 1.f,0,1, 0,0,0,0,0,0);
    gemm_nt<128,128,16,8,8,256><<<dim3(4,32,1),256>>>(memory, Wk, k_, bk, NTOK,512,512, 512,512,512, 1.f,0,1, 0,0,0,0,0,0);
    gemm_nt<128,128,16,8,8,256><<<dim3(4,32,1),256>>>(memory, Wv, v_, bv, NTOK,512,512, 512,512,512, 1.f,0,1, 0,0,0,0,0,0);
    // scores: per (b,h) 1024x1024x64, scaled by 1/8
    gemm_nt<128,128,16,8,8,256><<<dim3(8,8,32),256>>>(q_, k_, sc_, nullptr,
        1024,1024,64, 512,512,1024, 0.125f,0, NHEAD,
        (long)SEQ*DMODEL, (long)HDIM, (long)MEML*DMODEL, (long)HDIM,
        (long)NHEAD*SEQ*MEML, (long)SEQ*MEML);
    softmax_rows<<<BATCH*NHEAD*SEQ,256>>>(sc_);
    attn_pv<<<dim3(8,1,32),256>>>(sc_, v_, attn_);
    // output projection + residual LN
    gemm_nt<128,128,16,8,8,256><<<dim3(4,32,1),256>>>(attn_, Wo, tmp_, bo, NTOK,512,512, 512,512,512, 1.f,0,1, 0,0,0,0,0,0);
    ln_residual<<<NTOK,128>>>(x, tmp_, ln1_g, ln1_b, x1_);

    // ---- mamba ----
    gemm_nt<128,128,16,8,8,256><<<dim3(16,32,1),256>>>(x1_, W_in, xz_, nullptr, NTOK,2048,512, 512,512,2048, 1.f,0,1, 0,0,0,0,0,0);
    conv_silu<<<(NTOK*DINNER)/256,256>>>(xz_, conv_w, conv_b, u_);
    gemm_nt<64,64,16,4,4,256><<<dim3(1,64,1),256>>>(u_, W_xproj, xd_, nullptr, NTOK,64,1024, 1024,1024,64, 1.f,0,1, 0,0,0,0,0,0);
    gemm_nt<128,128,16,8,8,256><<<dim3(8,32,1),256>>>(xd_, W_dt, dt_, b_dt, NTOK,1024,32, 64,32,1024, 1.f,2,1, 0,0,0,0,0,0);
    scan_kernel<<<dim3(BATCH,DINNER/128),128>>>(xd_, dt_, u_, xz_, A_log, D_p, yg_);
    gemm_nt<128,128,16,8,8,256><<<dim3(4,32,1),256>>>(yg_, W_out, m_, nullptr, NTOK,512,1024, 1024,1024,512, 1.f,0,1, 0,0,0,0,0,0);
    ln_residual<<<NTOK,128>>>(x1_, m_, ln2_g, ln2_b, x2_);

    // ---- FFN ----
    gemm_nt<128,128,16,8,8,256><<<dim3(16,32,1),256>>>(x2_, W1, h1_, b1, NTOK,2048,512, 512,512,2048, 1.f,1,1, 0,0,0,0,0,0);
    gemm_nt<128,128,16,8,8,256><<<dim3(4,32,1),256>>>(h1_, W2, tmp_, b2, NTOK,512,2048, 2048,2048,512, 1.f,0,1, 0,0,0,0,0,0);
    ln_residual<<<NTOK,128>>>(x2_, tmp_, ln3_g, ln3_b, out);
}